// round 10
// baseline (speedup 1.0000x reference)
#include <cuda_runtime.h>

// Persistent single-wave grid-stride version: 1184 CTAs (148 SMs x 8 CTAs),
// each thread loops over 32B chunks with 2-deep unroll for MLP.
// Input reads: L2::evict_last (input stays resident across graph replays).
// Output stores: .cs evict-first (pure write stream, don't thrash input).

__device__ __forceinline__ void ld32_evict_last(const void* p, float4& a, float4& b) {
    unsigned long long r0, r1, r2, r3;
    asm volatile("ld.global.nc.L2::evict_last.v4.b64 {%0,%1,%2,%3}, [%4];"
                 : "=l"(r0), "=l"(r1), "=l"(r2), "=l"(r3)
                 : "l"(p));
    a.x = __uint_as_float((unsigned)r0); a.y = __uint_as_float((unsigned)(r0 >> 32));
    a.z = __uint_as_float((unsigned)r1); a.w = __uint_as_float((unsigned)(r1 >> 32));
    b.x = __uint_as_float((unsigned)r2); b.y = __uint_as_float((unsigned)(r2 >> 32));
    b.z = __uint_as_float((unsigned)r3); b.w = __uint_as_float((unsigned)(r3 >> 32));
}

__device__ __forceinline__ void st32_cs(void* p, const float4& a, const float4& b) {
    unsigned long long r0 = (unsigned long long)__float_as_uint(a.x)
                          | ((unsigned long long)__float_as_uint(a.y) << 32);
    unsigned long long r1 = (unsigned long long)__float_as_uint(a.z)
                          | ((unsigned long long)__float_as_uint(a.w) << 32);
    unsigned long long r2 = (unsigned long long)__float_as_uint(b.x)
                          | ((unsigned long long)__float_as_uint(b.y) << 32);
    unsigned long long r3 = (unsigned long long)__float_as_uint(b.z)
                          | ((unsigned long long)__float_as_uint(b.w) << 32);
    asm volatile("st.global.cs.v4.b64 [%0], {%1,%2,%3,%4};"
                 :: "l"(p), "l"(r0), "l"(r1), "l"(r2), "l"(r3)
                 : "memory");
}

__device__ __forceinline__ void transform32(const float4& va, const float4& vb,
                                            float m00, float m01, float m10, float m11,
                                            float4& ra, float4& rb) {
    ra.x = fmaf(va.x, m00, va.y * m10);
    ra.y = fmaf(va.x, m01, va.y * m11);
    ra.z = fmaf(va.z, m00, va.w * m10);
    ra.w = fmaf(va.z, m01, va.w * m11);
    rb.x = fmaf(vb.x, m00, vb.y * m10);
    rb.y = fmaf(vb.x, m01, vb.y * m11);
    rb.z = fmaf(vb.z, m00, vb.w * m10);
    rb.w = fmaf(vb.z, m01, vb.w * m11);
}

__global__ void __launch_bounds__(256) fused_kernel(
    const char* __restrict__ xb, char* __restrict__ outb, int n32,
    const float* __restrict__ linMt, const int* __restrict__ Np,
    const float* __restrict__ xs, float* __restrict__ outs, int n_pairs)
{
    __shared__ float sM[4];
    if (threadIdx.x == 0) {
        int n = Np[0];
        float b00 = linMt[0], b01 = linMt[1];
        float b10 = linMt[2], b11 = linMt[3];
        float p00 = 1.f, p01 = 0.f, p10 = 0.f, p11 = 1.f;
        while (n > 0) {
            if (n & 1) {
                float t00 = fmaf(p00, b00, p01 * b10);
                float t01 = fmaf(p00, b01, p01 * b11);
                float t10 = fmaf(p10, b00, p11 * b10);
                float t11 = fmaf(p10, b01, p11 * b11);
                p00 = t00; p01 = t01; p10 = t10; p11 = t11;
            }
            n >>= 1;
            if (n > 0) {
                float s00 = fmaf(b00, b00, b01 * b10);
                float s01 = fmaf(b00, b01, b01 * b11);
                float s10 = fmaf(b10, b00, b11 * b10);
                float s11 = fmaf(b10, b01, b11 * b11);
                b00 = s00; b01 = s01; b10 = s10; b11 = s11;
            }
        }
        sM[0] = p00; sM[1] = p01; sM[2] = p10; sM[3] = p11;
    }
    __syncthreads();
    const float m00 = sM[0], m01 = sM[1], m10 = sM[2], m11 = sM[3];

    const int stride = gridDim.x * blockDim.x;       // threads total
    int i = blockIdx.x * blockDim.x + threadIdx.x;

    // Main loop: 2 independent 32B chunks in flight per iteration.
    for (; i + stride < n32; i += 2 * stride) {
        int i0 = i, i1 = i + stride;
        float4 va0, vb0, va1, vb1;
        ld32_evict_last(xb + (size_t)i0 * 32, va0, vb0);
        ld32_evict_last(xb + (size_t)i1 * 32, va1, vb1);
        float4 ra0, rb0, ra1, rb1;
        transform32(va0, vb0, m00, m01, m10, m11, ra0, rb0);
        transform32(va1, vb1, m00, m01, m10, m11, ra1, rb1);
        st32_cs(outb + (size_t)i0 * 32, ra0, rb0);
        st32_cs(outb + (size_t)i1 * 32, ra1, rb1);
    }
    // Remainder (at most one chunk per thread).
    for (; i < n32; i += stride) {
        float4 va, vb, ra, rb;
        ld32_evict_last(xb + (size_t)i * 32, va, vb);
        transform32(va, vb, m00, m01, m10, m11, ra, rb);
        st32_cs(outb + (size_t)i * 32, ra, rb);
    }

    // Tail: leftover state pairs if total floats % 8 != 0 (up to 3 pairs).
    if (blockIdx.x == 0 && threadIdx.x == 0) {
        for (int p = n32 * 4; p < n_pairs; p++) {
            float a = xs[2 * p + 0];
            float b = xs[2 * p + 1];
            outs[2 * p + 0] = fmaf(a, m00, b * m10);
            outs[2 * p + 1] = fmaf(a, m01, b * m11);
        }
    }
}

extern "C" void kernel_launch(void* const* d_in, const int* in_sizes, int n_in,
                              void* d_out, int out_size) {
    const float* x     = (const float*)d_in[0];   // (B, 2) float32
    const float* linMt = (const float*)d_in[1];   // (2, 2) float32
    const int*   Np    = (const int*)d_in[2];     // scalar N
    float* out = (float*)d_out;

    int total   = in_sizes[0];   // B * 2 floats
    int n32     = total / 8;     // 32-byte chunks (4 states each)
    int n_pairs = total / 2;

    int threads = 256;
    int blocks = 148 * 8;        // one full wave at occupancy 8
    // Don't launch more threads than chunks (tiny-input safety).
    int max_blocks = (n32 + threads - 1) / threads;
    if (max_blocks < 1) max_blocks = 1;
    if (blocks > max_blocks) blocks = max_blocks;

    fused_kernel<<<blocks, threads>>>((const char*)x, (char*)out, n32,
                                      linMt, Np, x, out, n_pairs);
}

// round 11
// speedup vs baseline: 1.0111x; 1.0111x over previous
#include <cuda_runtime.h>

// R7 base (static grid, 32B ld/st, evict_last input / .cs output) with the
// prologue hidden: streaming loads issue BEFORE the M-computation barrier,
// so thread 0's linMt DRAM load + serial FMA chain overlaps them.
#define VEC32 2   // 32-byte chunks per thread

__device__ __forceinline__ void ld32_evict_last(const void* p, float4& a, float4& b) {
    unsigned long long r0, r1, r2, r3;
    asm volatile("ld.global.nc.L2::evict_last.v4.b64 {%0,%1,%2,%3}, [%4];"
                 : "=l"(r0), "=l"(r1), "=l"(r2), "=l"(r3)
                 : "l"(p));
    a.x = __uint_as_float((unsigned)r0); a.y = __uint_as_float((unsigned)(r0 >> 32));
    a.z = __uint_as_float((unsigned)r1); a.w = __uint_as_float((unsigned)(r1 >> 32));
    b.x = __uint_as_float((unsigned)r2); b.y = __uint_as_float((unsigned)(r2 >> 32));
    b.z = __uint_as_float((unsigned)r3); b.w = __uint_as_float((unsigned)(r3 >> 32));
}

__device__ __forceinline__ void st32_cs(void* p, const float4& a, const float4& b) {
    unsigned long long r0 = (unsigned long long)__float_as_uint(a.x)
                          | ((unsigned long long)__float_as_uint(a.y) << 32);
    unsigned long long r1 = (unsigned long long)__float_as_uint(a.z)
                          | ((unsigned long long)__float_as_uint(a.w) << 32);
    unsigned long long r2 = (unsigned long long)__float_as_uint(b.x)
                          | ((unsigned long long)__float_as_uint(b.y) << 32);
    unsigned long long r3 = (unsigned long long)__float_as_uint(b.z)
                          | ((unsigned long long)__float_as_uint(b.w) << 32);
    asm volatile("st.global.cs.v4.b64 [%0], {%1,%2,%3,%4};"
                 :: "l"(p), "l"(r0), "l"(r1), "l"(r2), "l"(r3)
                 : "memory");
}

__global__ void __launch_bounds__(256) fused_kernel(
    const char* __restrict__ xb, char* __restrict__ outb, int n32,
    const float* __restrict__ linMt, const int* __restrict__ Np,
    const float* __restrict__ xs, float* __restrict__ outs, int n_pairs)
{
    __shared__ float sM[4];

    int base = (blockIdx.x * blockDim.x) * VEC32 + threadIdx.x;

    // 1) Issue streaming loads first — in flight while M is computed.
    float4 va[VEC32], vb[VEC32];
    bool ok[VEC32];
#pragma unroll
    for (int j = 0; j < VEC32; j++) {
        int idx = base + j * 256;
        ok[j] = idx < n32;
        if (ok[j]) ld32_evict_last(xb + (size_t)idx * 32, va[j], vb[j]);
    }

    // 2) Thread 0 computes M = linMt^N (fp32 binary exp) into smem.
    if (threadIdx.x == 0) {
        int n = Np[0];
        float b00 = linMt[0], b01 = linMt[1];
        float b10 = linMt[2], b11 = linMt[3];
        float p00 = 1.f, p01 = 0.f, p10 = 0.f, p11 = 1.f;
        while (n > 0) {
            if (n & 1) {
                float t00 = fmaf(p00, b00, p01 * b10);
                float t01 = fmaf(p00, b01, p01 * b11);
                float t10 = fmaf(p10, b00, p11 * b10);
                float t11 = fmaf(p10, b01, p11 * b11);
                p00 = t00; p01 = t01; p10 = t10; p11 = t11;
            }
            n >>= 1;
            if (n > 0) {
                float s00 = fmaf(b00, b00, b01 * b10);
                float s01 = fmaf(b00, b01, b01 * b11);
                float s10 = fmaf(b10, b00, b11 * b10);
                float s11 = fmaf(b10, b01, b11 * b11);
                b00 = s00; b01 = s01; b10 = s10; b11 = s11;
            }
        }
        sM[0] = p00; sM[1] = p01; sM[2] = p10; sM[3] = p11;
    }
    __syncthreads();
    const float m00 = sM[0], m01 = sM[1], m10 = sM[2], m11 = sM[3];

    // 3) Transform + store.
#pragma unroll
    for (int j = 0; j < VEC32; j++) {
        int idx = base + j * 256;
        if (ok[j]) {
            float4 ra, rb;
            ra.x = fmaf(va[j].x, m00, va[j].y * m10);
            ra.y = fmaf(va[j].x, m01, va[j].y * m11);
            ra.z = fmaf(va[j].z, m00, va[j].w * m10);
            ra.w = fmaf(va[j].z, m01, va[j].w * m11);
            rb.x = fmaf(vb[j].x, m00, vb[j].y * m10);
            rb.y = fmaf(vb[j].x, m01, vb[j].y * m11);
            rb.z = fmaf(vb[j].z, m00, vb[j].w * m10);
            rb.w = fmaf(vb[j].z, m01, vb[j].w * m11);
            st32_cs(outb + (size_t)idx * 32, ra, rb);
        }
    }

    // Tail: leftover state pairs if total floats % 8 != 0 (up to 3 pairs).
    if (blockIdx.x == 0 && threadIdx.x == 0) {
        for (int p = n32 * 4; p < n_pairs; p++) {
            float a = xs[2 * p + 0];
            float b = xs[2 * p + 1];
            outs[2 * p + 0] = fmaf(a, m00, b * m10);
            outs[2 * p + 1] = fmaf(a, m01, b * m11);
        }
    }
}

extern "C" void kernel_launch(void* const* d_in, const int* in_sizes, int n_in,
                              void* d_out, int out_size) {
    const float* x     = (const float*)d_in[0];   // (B, 2) float32
    const float* linMt = (const float*)d_in[1];   // (2, 2) float32
    const int*   Np    = (const int*)d_in[2];     // scalar N
    float* out = (float*)d_out;

    int total   = in_sizes[0];   // B * 2 floats
    int n32     = total / 8;     // 32-byte chunks (4 states each)
    int n_pairs = total / 2;

    int threads = 256;
    int per_block = threads * VEC32;
    int blocks = (n32 + per_block - 1) / per_block;
    if (blocks < 1) blocks = 1;

    fused_kernel<<<blocks, threads>>>((const char*)x, (char*)out, n32,
                                      linMt, Np, x, out, n_pairs);
}